// round 5
// baseline (speedup 1.0000x reference)
#include <cuda_runtime.h>
#include <math.h>

// Problem constants
#define NB 32     // batch
#define SS 12     // seq len
#define FF 128    // features
#define KH 8      // heads
#define HH 64     // head dim
#define CC 64     // out channels
#define NN 512    // nodes
#define SEGS 8    // n-segments for Wf reduction (512/8 = 64 rows/segment)

#define WF_BLOCKS (CC * SEGS)            // 512 wfsum blocks
#define TOTAL_BLOCKS (WF_BLOCKS + NB)    // + 32 feature blocks = 544

// Scratch (no allocations allowed)
__device__ float g_v[NB * CC];              // per-batch feature vector v[b][c]
__device__ float g_wfpart[CC * SEGS * CC];  // partials, layout [c2][seg][c]
__device__ unsigned int g_done;             // arrival counter (zero-init, self-resetting)

// Shared scratch (union across the three roles)
//  wf:      sred    1024 floats
//  feature: xl 128 + hp 512 + red 256 = 896 floats
//  finale:  sv 2048 + sw 64*68=4352 + sbf 64 = 6464 floats
#define SV_OFF  0
#define SW_OFF  2048
#define SBF_OFF 6400
#define SBUF_FLOATS 6464

__global__ void __launch_bounds__(256) kFused(
    const float* __restrict__ Wf,
    const float* __restrict__ x,
    const float* __restrict__ W_heads,
    const float* __restrict__ W_out,
    const float* __restrict__ bf,
    float* __restrict__ out)
{
    __shared__ __align__(16) float sbuf[SBUF_FLOATS];
    int bid = blockIdx.x;
    int tid = threadIdx.x;

    if (bid < WF_BLOCKS) {
        // ---------------- Wf segment reduction ----------------
        // g_wfpart[c2][seg][c] = sum_{n in seg} Wf[c2][n*64 + c]
        int c2  = bid >> 3;          // 0..63
        int seg = bid & 7;           // 0..7
        int lane = tid & 15;         // float4 index within 64-float row
        int np   = tid >> 4;         // 16 n-partitions, 4 rows each

        const float4* base = (const float4*)(Wf + (size_t)c2 * (NN * CC));

        int n0 = seg * 64 + np * 4;
        float4 v0 = base[(n0 + 0) * 16 + lane];
        float4 v1 = base[(n0 + 1) * 16 + lane];
        float4 v2 = base[(n0 + 2) * 16 + lane];
        float4 v3 = base[(n0 + 3) * 16 + lane];
        float4 acc;
        acc.x = (v0.x + v1.x) + (v2.x + v3.x);
        acc.y = (v0.y + v1.y) + (v2.y + v3.y);
        acc.z = (v0.z + v1.z) + (v2.z + v3.z);
        acc.w = (v0.w + v1.w) + (v2.w + v3.w);

        float4* sred = (float4*)sbuf;
        sred[tid] = acc;
        __syncthreads();
        #pragma unroll
        for (int s = 8; s >= 1; s >>= 1) {
            if (np < s) {
                float4 o = sred[(np + s) * 16 + lane];
                float4 m = sred[np * 16 + lane];
                m.x += o.x; m.y += o.y; m.z += o.z; m.w += o.w;
                sred[np * 16 + lane] = m;
            }
            __syncthreads();
        }
        if (tid < 16) {
            ((float4*)(g_wfpart + ((size_t)c2 * SEGS + seg) * CC))[lane] = sred[lane];
        }
    } else {
        // ---------------- per-batch feature vector ----------------
        // v[b][c] = sum_j elu( x_last[b] . W_heads[:,:,j] ) * W_out[j][c]
        int b = bid - WF_BLOCKS;

        float* xl  = sbuf;            // 128
        float* hp  = sbuf + 128;      // 512
        float* red = sbuf + 640;      // 256

        if (tid < FF) xl[tid] = x[b * SS * FF + (SS - 1) * FF + tid];
        __syncthreads();

        #pragma unroll
        for (int rep = 0; rep < 2; ++rep) {
            int j = tid + rep * 256;
            int k = j >> 6;
            int h = j & 63;
            const float* w = W_heads + (k * FF) * HH + h;   // lanes contiguous in h
            float acc = 0.f;
            #pragma unroll 8
            for (int f = 0; f < FF; ++f)
                acc = fmaf(xl[f], w[f * HH], acc);
            hp[j] = (acc > 0.f) ? acc : expm1f(acc);   // elu (alpha=1)
        }
        __syncthreads();

        {
            int c = tid & 63;
            int part = tid >> 6;
            float acc = 0.f;
            int j0 = part * 128;
            #pragma unroll 8
            for (int j = j0; j < j0 + 128; ++j)
                acc = fmaf(hp[j], W_out[j * CC + c], acc);
            red[part * 64 + c] = acc;
        }
        __syncthreads();
        #pragma unroll
        for (int s = 2; s >= 1; s >>= 1) {
            int c = tid & 63;
            int part = tid >> 6;
            if (part < s) red[part * 64 + c] += red[(part + s) * 64 + c];
            __syncthreads();
        }
        if (tid < CC) g_v[b * CC + tid] = red[tid];
    }

    // ---------------- arrive; last block does the finale ----------------
    __shared__ unsigned int s_last;
    __threadfence();                 // release: make this block's writes visible
    __syncthreads();                 // all threads' stores done before arrive
    if (tid == 0) {
        unsigned int old = atomicAdd(&g_done, 1u);
        s_last = (old == TOTAL_BLOCKS - 1) ? 1u : 0u;
        if (s_last) g_done = 0;      // reset for next launch/replay (we are alone)
    }
    __syncthreads();
    if (!s_last) return;
    __threadfence();                 // acquire side

    // ---------------- finale (one block, data L2-resident) ----------------
    float4* sv4 = (float4*)(sbuf + SV_OFF);     // 512 float4  (v, all batches)
    float4* sw4 = (float4*)(sbuf + SW_OFF);     // 64 rows x 17 float4 (padded)
    float*  sbf = sbuf + SBF_OFF;               // 64

    // g_v -> shared (2 float4 / thread)
    const float4* gv4 = (const float4*)g_v;
    sv4[tid]       = gv4[tid];
    sv4[tid + 256] = gv4[tid + 256];
    if (tid < CC) sbf[tid] = bf[tid];

    // sw[c2][c] = sum_seg g_wfpart[c2][seg][c]   (4 items/thread, 8 loads each)
    const float4* p4 = (const float4*)g_wfpart;
    #pragma unroll
    for (int k = 0; k < 4; ++k) {
        int item = tid + k * 256;     // 1024 items = 64 c2 x 16 lanes
        int c2i  = item >> 4;
        int ln   = item & 15;
        const float4* row = p4 + (size_t)c2i * (SEGS * 16) + ln;
        float4 s = make_float4(0.f, 0.f, 0.f, 0.f);
        #pragma unroll
        for (int seg = 0; seg < SEGS; ++seg) {
            float4 t = row[seg * 16];
            s.x += t.x; s.y += t.y; s.z += t.z; s.w += t.w;
        }
        sw4[c2i * 17 + ln] = s;
    }
    __syncthreads();

    // out[b][c2] = bf[c2] + dot(v[b], sw[c2])   (8 outputs/thread)
    {
        int b = tid >> 3;             // 0..31
        const float4* svb = sv4 + b * 16;
        #pragma unroll
        for (int k = 0; k < 8; ++k) {
            int c2o = (tid & 7) + k * 8;
            const float4* swr = sw4 + c2o * 17;
            float acc = sbf[c2o];
            #pragma unroll
            for (int j = 0; j < 16; ++j) {
                float4 a = svb[j];
                float4 w = swr[j];
                acc = fmaf(a.x, w.x, acc);
                acc = fmaf(a.y, w.y, acc);
                acc = fmaf(a.z, w.z, acc);
                acc = fmaf(a.w, w.w, acc);
            }
            out[b * CC + c2o] = acc;
        }
    }
}

// ---------------------------------------------------------------------------
// Inputs (metadata order):
//   0: x        (32,12,128)   f32
//   1: W_heads  (8,128,64)    f32
//   2: a1_heads (8,64)        f32   (unused: softmax over identical rows is uniform)
//   3: a2_heads (8,64)        f32   (unused)
//   4: W_out    (512,64)      f32
//   5: a1_out   (64)          f32   (unused)
//   6: a2_out   (64)          f32   (unused)
//   7: Wf       (64,32768)    f32
//   8: bf       (64)          f32
// Output: (32,64) f32
// ---------------------------------------------------------------------------
extern "C" void kernel_launch(void* const* d_in, const int* in_sizes, int n_in,
                              void* d_out, int out_size)
{
    const float* x       = (const float*)d_in[0];
    const float* W_heads = (const float*)d_in[1];
    const float* W_out   = (const float*)d_in[4];
    const float* Wf      = (const float*)d_in[7];
    const float* bf      = (const float*)d_in[8];
    float* out = (float*)d_out;

    kFused<<<TOTAL_BLOCKS, 256>>>(Wf, x, W_heads, W_out, bf, out);
}